// round 10
// baseline (speedup 1.0000x reference)
#include <cuda_runtime.h>
#include <cstdint>
#include <math.h>

// Problem constants
#define Bp   4096
#define Dd   19
#define Ff   64
#define NCc  256
#define HIDh 32
#define SQq  16
#define Nn   (Bp + NCc)
#define PD   20            // padded row stride (19 + 1 zero pad)
#define PD4  5             // PD/4 (float4 granules)

// Tiling
#define JT   128            // j per tile
#define NJT  (Nn / JT)      // 34
#define NPJT (Bp / JT)      // 32 patient-only tiles
#define IT   16             // centers per tile-task
#define NIT  (NCc / IT)     // 16
#define NTASK (NJT * NIT)   // 544

// Persistent grid
#define NBLK 148
#define NTHR 256
#define NT_ALL (NBLK * NTHR)       // 37888

// Output offsets (floats)
#define OUT_GS  0
#define OUT_GE  (Bp * Dd)
#define OUT_GPE ((Bp + NCc) * Dd)
#define OUT_GL  (((2 * Bp) + NCc) * Dd)

typedef unsigned long long u64;

// -------- device scratch (no allocations allowed) --------
__device__ float4 g_x4[Nn * PD4];
__device__ float4 g_e4[Nn * PD4];
__device__ float  g_party[NJT * NCc * PD];  // y-partials: (adj@x) rows
__device__ u64    g_key[Bp * NIT];          // [patient][center-tile]
__device__ float  g_ge[NCc * Dd];
__device__ float  g_sc[NCc * Dd];

// grid barrier state (zero-init at load; returns to steady state each run)
__device__ unsigned g_bar_count;
__device__ volatile unsigned g_bar_sense;

__device__ __forceinline__ void grid_barrier(unsigned* sense0) {
    __syncthreads();
    if (threadIdx.x == 0) {
        unsigned next = *sense0 ^ 1u;
        __threadfence();
        if (atomicAdd(&g_bar_count, 1u) == gridDim.x - 1u) {
            g_bar_count = 0u;
            __threadfence();
            g_bar_sense = next;
        } else {
            while (g_bar_sense != next) { }
        }
        __threadfence();
        *sense0 = next;
    }
    __syncthreads();
}

// packed f32x2 fma: d = a*b + d
__device__ __forceinline__ void ffma2(u64& d, u64 a, u64 b) {
    asm("fma.rn.f32x2 %0, %1, %2, %0;" : "+l"(d) : "l"(a), "l"(b));
}
__device__ __forceinline__ float lo32(u64 v) {
    return __uint_as_float((unsigned)(v & 0xFFFFFFFFull));
}
__device__ __forceinline__ float hi32(u64 v) {
    return __uint_as_float((unsigned)(v >> 32));
}
__device__ __forceinline__ u64 pack2(float a, float b) {
    u64 r;
    asm("mov.b64 %0, {%1, %2};" : "=l"(r) : "r"(__float_as_uint(a)), "r"(__float_as_uint(b)));
    return r;
}

// -------- shared memory (union across phases) --------
struct SmP1 {
    float spw[61 * Dd];     // proj_w (block 8)
    float spb[Dd];
};
struct SmP2 {
    ulonglong2 sxu[JT * PD4];
    ulonglong2 seu[JT * PD4];
    float ssq[JT];
    u64   skey[8][JT + 1];
};
struct SmP3 {
    float sp[2][4 * PD];    // per-warp Y partials
    float sy[2][PD];        // reduced Y
    float seh[2][HIDh];
    float semb[2][PD];
    float shq[2][SQq];
};
union SmemU {
    SmP1 p1;
    SmP2 p2;
    SmP3 p3;
};

// ============================================================
__global__ void __launch_bounds__(NTHR) fused_all(
        const float* __restrict__ x,
        const float* __restrict__ dc,
        const float* __restrict__ centers,
        const float* __restrict__ proj_w,
        const float* __restrict__ proj_b,
        const float* __restrict__ p_ptr,
        const float* __restrict__ cc,
        const float* __restrict__ gcn_w,
        const float* __restrict__ gcn_b,
        const float* __restrict__ out_w,
        const float* __restrict__ out_b,
        const float* __restrict__ w1,
        const float* __restrict__ b1,
        const float* __restrict__ w2,
        const float* __restrict__ b2,
        float* __restrict__ out) {
    __shared__ SmemU sm;
    __shared__ int slabel[32];

    int tid = threadIdx.x;
    int wid = tid >> 5, lane = tid & 31;
    int bx = blockIdx.x;
    int gt = bx * NTHR + tid;

    unsigned sense0 = 0;
    if (tid == 0) sense0 = g_bar_sense;

    float p = *p_ptr;
    float c1 = 1.0f - p;

    float* gx = (float*)g_x4;
    float* ge = (float*)g_e4;

    // ======================= P1: prep =======================
    {
        // x mean: one thread per (b,d) row, emulating the exact warp-tree
        // reduction order of the validated kernels:
        //   v[l] = x[l] + x[l+32];  for d in {16,8,4,2,1}: v[l] += v[l+d]
        for (int r = gt; r < Bp * Dd; r += NT_ALL) {
            const float4* src = (const float4*)x + (size_t)r * 16;
            float xs[64];
            #pragma unroll
            for (int i = 0; i < 16; i++) {
                float4 a = src[i];
                xs[4 * i]     = a.x;
                xs[4 * i + 1] = a.y;
                xs[4 * i + 2] = a.z;
                xs[4 * i + 3] = a.w;
            }
            float v[32];
            #pragma unroll
            for (int l = 0; l < 32; l++) v[l] = xs[l] + xs[l + 32];
            #pragma unroll
            for (int d = 16; d >= 1; d >>= 1) {
                #pragma unroll
                for (int l = 0; l < 16; l++) {
                    if (l < d) v[l] = v[l] + v[l + d];
                }
            }
            int b = r / Dd, d2 = r - b * Dd;
            gx[b * PD + d2] = v[0] * (1.0f / 64.0f);
        }

        // e = exp(1 - dc) for patients
        for (int idx = gt; idx < Bp * Dd; idx += NT_ALL) {
            int b = idx / Dd, k = idx - b * Dd;
            ge[b * PD + k] = expf(1.0f - dc[idx]);
        }
        // pad slot = 0 for all rows
        for (int i = gt; i < Nn; i += NT_ALL) {
            gx[i * PD + Dd] = 0.0f;
            ge[i * PD + Dd] = 0.0f;
        }

        // centers (block 8): thread-per-center, sequential m order
        if (bx == 8) {
            for (int i = tid; i < 61 * Dd; i += NTHR) sm.p1.spw[i] = proj_w[i];
            if (tid < Dd) sm.p1.spb[tid] = proj_b[tid];
            __syncthreads();

            int c = tid;
            float cp[Dd];
            #pragma unroll
            for (int k = 0; k < Dd; k++) cp[k] = sm.p1.spb[k];
            for (int m = 0; m < 61; m++) {
                float cm = centers[c * 61 + m];
                #pragma unroll
                for (int k = 0; k < Dd; k++) cp[k] += cm * sm.p1.spw[m * Dd + k];
            }
            int row = Bp + c;
            #pragma unroll
            for (int k = 0; k < Dd; k++) {
                gx[row * PD + k] = cp[k];
                ge[row * PD + k] = expf(1.0f - cc[c * Dd + k]);
            }
            gx[row * PD + Dd] = 0.0f;
            ge[row * PD + Dd] = 0.0f;
        }
    }

    grid_barrier(&sense0);

    // ======================= P2: adjacency + (adj@x) + keys =======================
    {
        const ulonglong2* gxu = (const ulonglong2*)g_x4;
        const ulonglong2* geu = (const ulonglong2*)g_e4;
        int cpi = tid >> 5, s = tid & 31;

        for (int t = bx; t < NTASK; t += NBLK) {
            int jt = t / NIT, it = t - (t / NIT) * NIT;
            int j0 = jt * JT;
            bool ptile = (jt < NPJT);

            __syncthreads();   // close previous task's smem use

            for (int i = tid; i < JT * PD4; i += NTHR) {
                sm.p2.sxu[i] = gxu[j0 * PD4 + i];
                sm.p2.seu[i] = geu[j0 * PD4 + i];
            }
            __syncthreads();

            // ssq from tile: SEQUENTIAL scalar order (matches validated g_sq)
            if (tid < JT) {
                const float* xs = (const float*)sm.p2.sxu + tid * PD;
                float ss = 0.0f;
                #pragma unroll
                for (int k = 0; k < Dd; k++) ss += xs[k] * xs[k];
                sm.p2.ssq[tid] = ss;
            }

            int cA = it * IT + cpi * 2;
            int cB = cA + 1;
            int cgA = Bp + cA, cgB = Bp + cB;

            ulonglong2 xA[PD4], eA[PD4], xB[PD4], eB[PD4];
            #pragma unroll
            for (int q = 0; q < PD4; q++) {
                xA[q] = gxu[cgA * PD4 + q];
                eA[q] = geu[cgA * PD4 + q];
                xB[q] = gxu[cgB * PD4 + q];
                eB[q] = geu[cgB * PD4 + q];
            }
            // sqA/sqB: sequential scalar order over the 19 real elements
            float fxA[PD], fxB[PD];
            #pragma unroll
            for (int q = 0; q < PD4; q++) {
                fxA[4 * q]     = lo32(xA[q].x);
                fxA[4 * q + 1] = hi32(xA[q].x);
                fxA[4 * q + 2] = lo32(xA[q].y);
                fxA[4 * q + 3] = hi32(xA[q].y);
                fxB[4 * q]     = lo32(xB[q].x);
                fxB[4 * q + 1] = hi32(xB[q].x);
                fxB[4 * q + 2] = lo32(xB[q].y);
                fxB[4 * q + 3] = hi32(xB[q].y);
            }
            float sqA = 0.0f, sqB = 0.0f;
            #pragma unroll
            for (int k = 0; k < Dd; k++) {
                sqA += fxA[k] * fxA[k];
                sqB += fxB[k] * fxB[k];
            }
            __syncthreads();

            u64 yA[2 * PD4], yB[2 * PD4];
            #pragma unroll
            for (int m = 0; m < 2 * PD4; m++) { yA[m] = 0ull; yB[m] = 0ull; }

            #pragma unroll
            for (int tt = 0; tt < JT / 32; tt++) {
                int j = s + 32 * tt;
                ulonglong2 vv[PD4], ww[PD4];
                #pragma unroll
                for (int q = 0; q < PD4; q++) {
                    vv[q] = sm.p2.sxu[j * PD4 + q];
                    ww[q] = sm.p2.seu[j * PD4 + q];
                }
                u64 dxA2 = 0ull, deA2 = 0ull, dxB2 = 0ull, deB2 = 0ull;
                #pragma unroll
                for (int q = 0; q < PD4; q++) {
                    ffma2(dxA2, xA[q].x, vv[q].x);  ffma2(dxA2, xA[q].y, vv[q].y);
                    ffma2(deA2, eA[q].x, ww[q].x);  ffma2(deA2, eA[q].y, ww[q].y);
                    ffma2(dxB2, xB[q].x, vv[q].x);  ffma2(dxB2, xB[q].y, vv[q].y);
                    ffma2(deB2, eB[q].x, ww[q].x);  ffma2(deB2, eB[q].y, ww[q].y);
                }
                float dxA = lo32(dxA2) + hi32(dxA2);
                float deA = lo32(deA2) + hi32(deA2);
                float dxB = lo32(dxB2) + hi32(dxB2);
                float deB = lo32(deB2) + hi32(deB2);

                int jg = j0 + j;
                float denA = c1 * (sqA + sm.p2.ssq[j] - 2.0f * dxA) + p * deA;
                float denB = c1 * (sqB + sm.p2.ssq[j] - 2.0f * dxB) + p * deB;
                float aA = (jg == cgA) ? 1.0f : __fdividef((float)Dd, denA);
                float aB = (jg == cgB) ? 1.0f : __fdividef((float)Dd, denB);

                if (ptile) {
                    u64 kA = (((u64)__float_as_uint(denA)) << 32) | (unsigned)cA;
                    u64 kB = (((u64)__float_as_uint(denB)) << 32) | (unsigned)cB;
                    sm.p2.skey[cpi][j] = (kA < kB) ? kA : kB;
                }

                u64 a2A = pack2(aA, aA);
                u64 a2B = pack2(aB, aB);
                #pragma unroll
                for (int q = 0; q < PD4; q++) {
                    ffma2(yA[2 * q],     a2A, vv[q].x);
                    ffma2(yA[2 * q + 1], a2A, vv[q].y);
                    ffma2(yB[2 * q],     a2B, vv[q].x);
                    ffma2(yB[2 * q + 1], a2B, vv[q].y);
                }
            }

            if (ptile) {
                __syncthreads();
                if (tid < JT) {
                    u64 m = sm.p2.skey[0][tid];
                    #pragma unroll
                    for (int q = 1; q < 8; q++) {
                        u64 v = sm.p2.skey[q][tid];
                        if (v < m) m = v;
                    }
                    g_key[(size_t)(j0 + tid) * NIT + it] = m;
                }
            }

            // unpack; butterfly -> lane s holds elem s
            float fA[32], fB[32];
            #pragma unroll
            for (int m = 0; m < 2 * PD4; m++) {
                fA[2 * m] = lo32(yA[m]);  fA[2 * m + 1] = hi32(yA[m]);
                fB[2 * m] = lo32(yB[m]);  fB[2 * m + 1] = hi32(yB[m]);
            }
            #pragma unroll
            for (int m = 2 * PD4 * 2; m < 32; m++) { fA[m] = 0.0f; fB[m] = 0.0f; }
            #pragma unroll
            for (int d = 16; d >= 1; d >>= 1) {
                #pragma unroll
                for (int i = 0; i < d; i++) {
                    float sendA = (s & d) ? fA[i] : fA[i + d];
                    float sendB = (s & d) ? fB[i] : fB[i + d];
                    float recvA = __shfl_xor_sync(0xffffffffu, sendA, d);
                    float recvB = __shfl_xor_sync(0xffffffffu, sendB, d);
                    fA[i] = ((s & d) ? fA[i + d] : fA[i]) + recvA;
                    fB[i] = ((s & d) ? fB[i + d] : fB[i]) + recvB;
                }
            }
            if (s < PD) {
                g_party[((size_t)jt * NCc + cA) * PD + s] = fA[0];
                g_party[((size_t)jt * NCc + cB) * PD + s] = fB[0];
            }
        }
    }

    grid_barrier(&sense0);

    // ============== P4a: labels (keys final) — overlaps P3 ==============
    if (bx < Bp / 32) {
        int pl = tid >> 3, l8 = tid & 7;
        int jp = bx * 32 + pl;
        ulonglong2 kv = ((const ulonglong2*)g_key)[(size_t)jp * 8 + l8];
        u64 best = (kv.x < kv.y) ? kv.x : kv.y;
        u64 o;
        o = __shfl_xor_sync(0xffffffffu, best, 1); if (o < best) best = o;
        o = __shfl_xor_sync(0xffffffffu, best, 2); if (o < best) best = o;
        o = __shfl_xor_sync(0xffffffffu, best, 4); if (o < best) best = o;
        if (l8 == 0) slabel[pl] = (int)(unsigned)(best & 0xFFFFFFFFull);
    }

    // ======================= P3: center MLP chain =======================
    {
        int half = wid >> 2;                 // 0/1
        int w4 = wid & 3;
        int c = bx * 2 + half;
        bool active = (bx < NCc / 2);

        float ps = 0.0f;
        if (active && lane < PD) {
            int jt0 = w4 * 9;
            int jt1 = (w4 == 3) ? NJT : jt0 + 9;
            const float* pp = &g_party[(size_t)c * PD + lane];
            #pragma unroll 9
            for (int jt = jt0; jt < jt1; jt++)
                ps += pp[(size_t)jt * (NCc * PD)];
        }
        if (lane < PD) sm.p3.sp[half][w4 * PD + lane] = ps;
        __syncthreads();

        if (w4 == 0 && active) {
            int h = lane;
            if (lane < PD) {
                const float* spv = sm.p3.sp[half];
                sm.p3.sy[half][lane] = spv[lane] + spv[PD + lane]
                                     + spv[2 * PD + lane] + spv[3 * PD + lane];
            }
            __syncwarp();

            // eh[h] = gcn_b[h] + sum_k Y[k] * gcn_w[k][h]
            float eh = gcn_b[h];
            #pragma unroll
            for (int k = 0; k < Dd; k++)
                eh += sm.p3.sy[half][k] * gcn_w[k * HIDh + h];
            sm.p3.seh[half][h] = eh;
            __syncwarp();

            if (h < Dd) {
                float v = out_b[h];
                #pragma unroll
                for (int q = 0; q < HIDh; q++) v += sm.p3.seh[half][q] * out_w[q * Dd + h];
                v = 1.0f / (1.0f + expf(-v));
                sm.p3.semb[half][h] = v;
                g_ge[c * Dd + h] = v;
                out[OUT_GE + c * Dd + h] = v;
            }
            __syncwarp();

            if (h < SQq) {
                float v = b1[h];
                #pragma unroll
                for (int k = 0; k < Dd; k++) v += sm.p3.semb[half][k] * w1[k * SQq + h];
                sm.p3.shq[half][h] = 0.5f * v * (1.0f + erff(v * 0.70710678118654752f));
            }
            __syncwarp();

            if (h < Dd) {
                float v = b2[h];
                #pragma unroll
                for (int q = 0; q < SQq; q++) v += sm.p3.shq[half][q] * w2[q * Dd + h];
                g_sc[c * Dd + h] = 1.0f / (1.0f + expf(-v));
            }
        }
    }

    grid_barrier(&sense0);

    // ======================= P4b: gather =======================
    if (bx < Bp / 32) {
        int pl = tid >> 3, l8 = tid & 7;
        int jp = bx * 32 + pl;
        int label = slabel[pl];
        #pragma unroll
        for (int k = l8; k < Dd; k += 8) {
            out[OUT_GS + jp * Dd + k]  = g_sc[label * Dd + k];
            out[OUT_GPE + jp * Dd + k] = g_ge[label * Dd + k];
        }
        if (l8 == 0) out[OUT_GL + jp] = (float)label;
    }
}

// ============================================================
extern "C" void kernel_launch(void* const* d_in, const int* in_sizes, int n_in,
                              void* d_out, int out_size) {
    const float* x        = (const float*)d_in[0];
    const float* dc       = (const float*)d_in[1];
    const float* centers  = (const float*)d_in[2];
    const float* proj_w   = (const float*)d_in[3];
    const float* proj_b   = (const float*)d_in[4];
    const float* dc_param = (const float*)d_in[5];
    const float* cc       = (const float*)d_in[6];
    const float* gcn_w    = (const float*)d_in[7];
    const float* gcn_b    = (const float*)d_in[8];
    const float* out_w    = (const float*)d_in[9];
    const float* out_b    = (const float*)d_in[10];
    const float* w1       = (const float*)d_in[11];
    const float* b1       = (const float*)d_in[12];
    const float* w2       = (const float*)d_in[13];
    const float* b2       = (const float*)d_in[14];
    float* out = (float*)d_out;

    fused_all<<<NBLK, NTHR>>>(x, dc, centers, proj_w, proj_b, dc_param, cc,
                              gcn_w, gcn_b, out_w, out_b, w1, b1, w2, b2, out);
}